// round 1
// baseline (speedup 1.0000x reference)
#include <cuda_runtime.h>
#include <cstdint>

// Problem constants (fixed shapes from the reference)
#define LOCN  10000   // location vocab / A dimension
#define DLOC  128     // d_model for location branch
#define DST   64      // d_model for start-time / end branch
#define DSUM  256     // DLOC + DST + DST
#define BB    64      // batch
#define SS    128     // sequence length

// Scratch: Y = A @ W_loc, [LOCN, DLOC] fp32 (5.12 MB). Recomputed every launch.
__device__ float g_Y[(size_t)LOCN * DLOC];

// ---------------------------------------------------------------------------
// Kernel 1: sparse-aware Y = A @ W_loc.
// One warp per row of A. Stream the 40 KB row as float4 (coalesced), ballot
// over nonzero vectors (~0.1% density), broadcast hits via shfl, and
// accumulate val * W_loc[n][d] into 4 registers per lane (d = lane + 32k).
// HBM-bound: 400 MB read of A dominates; W_loc (5 MB) stays L2-resident.
// ---------------------------------------------------------------------------
__global__ void __launch_bounds__(256) spmm_rows_kernel(
    const float* __restrict__ A, const float* __restrict__ W)
{
    const int warp_id = (blockIdx.x * blockDim.x + threadIdx.x) >> 5;
    const int lane    = threadIdx.x & 31;
    if (warp_id >= LOCN) return;

    const float4* __restrict__ row =
        reinterpret_cast<const float4*>(A + (size_t)warp_id * LOCN);

    float acc0 = 0.f, acc1 = 0.f, acc2 = 0.f, acc3 = 0.f;

    constexpr int NV4   = LOCN / 4;            // 2500 float4 per row
    constexpr int NITER = (NV4 + 31) / 32;     // 79

    for (int it = 0; it < NITER; ++it) {
        const int base = it * 32 + lane;
        float4 v;
        if (base < NV4) {
            v = row[base];
        } else {
            v.x = v.y = v.z = v.w = 0.f;
        }
        const bool nz = (v.x != 0.f) | (v.y != 0.f) | (v.z != 0.f) | (v.w != 0.f);
        unsigned m = __ballot_sync(0xffffffffu, nz);

        while (m) {
            const int j = __ffs(m) - 1;
            m &= m - 1;
            const float vx = __shfl_sync(0xffffffffu, v.x, j);
            const float vy = __shfl_sync(0xffffffffu, v.y, j);
            const float vz = __shfl_sync(0xffffffffu, v.z, j);
            const float vw = __shfl_sync(0xffffffffu, v.w, j);
            const int n0 = (it * 32 + j) * 4;   // column of v.x

            const float* __restrict__ Wr = W + (size_t)n0 * DLOC + lane;
            if (vx != 0.f) {
                acc0 = fmaf(vx, Wr[0],  acc0);
                acc1 = fmaf(vx, Wr[32], acc1);
                acc2 = fmaf(vx, Wr[64], acc2);
                acc3 = fmaf(vx, Wr[96], acc3);
            }
            Wr += DLOC;
            if (vy != 0.f) {
                acc0 = fmaf(vy, Wr[0],  acc0);
                acc1 = fmaf(vy, Wr[32], acc1);
                acc2 = fmaf(vy, Wr[64], acc2);
                acc3 = fmaf(vy, Wr[96], acc3);
            }
            Wr += DLOC;
            if (vz != 0.f) {
                acc0 = fmaf(vz, Wr[0],  acc0);
                acc1 = fmaf(vz, Wr[32], acc1);
                acc2 = fmaf(vz, Wr[64], acc2);
                acc3 = fmaf(vz, Wr[96], acc3);
            }
            Wr += DLOC;
            if (vw != 0.f) {
                acc0 = fmaf(vw, Wr[0],  acc0);
                acc1 = fmaf(vw, Wr[32], acc1);
                acc2 = fmaf(vw, Wr[64], acc2);
                acc3 = fmaf(vw, Wr[96], acc3);
            }
        }
    }

    float* __restrict__ y = g_Y + (size_t)warp_id * DLOC + lane;
    y[0]  = acc0;
    y[32] = acc1;
    y[64] = acc2;
    y[96] = acc3;
}

// ---------------------------------------------------------------------------
// Kernel 2: assemble outputs.
//   out[0 : B*S*256)          = concat(relu(Y[loc]+b), emb_st[st], emb_ed[ed]) * 16
//   out[B*S*256 : +B*S*64)    = emb_st[yt],  yt[b,s] = st[b,s+1] (0 for s=S-1)
// One thread per output element; fully coalesced writes.
// ---------------------------------------------------------------------------
__global__ void __launch_bounds__(256) gather_concat_kernel(
    const int*   __restrict__ loc,
    const int*   __restrict__ st,
    const int*   __restrict__ ed,
    const float* __restrict__ bias,
    const float* __restrict__ emb_st,
    const float* __restrict__ emb_ed,
    float*       __restrict__ out)
{
    const int idx = blockIdx.x * blockDim.x + threadIdx.x;
    constexpr int N1 = BB * SS * DSUM;           // 2,097,152
    constexpr int NT = N1 + BB * SS * DST;       // 2,621,440
    if (idx >= NT) return;

    const float scale = 16.0f;                   // sqrt(256)

    if (idx < N1) {
        const int bs = idx >> 8;                 // / DSUM
        const int d  = idx & 255;
        float r;
        if (d < DLOC) {
            r = g_Y[(size_t)loc[bs] * DLOC + d] + bias[d];
            r = r > 0.f ? r : 0.f;
        } else if (d < DLOC + DST) {
            r = emb_st[st[bs] * DST + (d - DLOC)];
        } else {
            r = emb_ed[ed[bs] * DST + (d - DLOC - DST)];
        }
        out[idx] = r * scale;
    } else {
        const int j  = idx - N1;
        const int bs = j >> 6;                   // / DST
        const int d  = j & 63;
        const int s  = bs & (SS - 1);
        const int yt = (s < SS - 1) ? st[bs + 1] : 0;
        out[idx] = emb_st[yt * DST + d];
    }
}

extern "C" void kernel_launch(void* const* d_in, const int* in_sizes, int n_in,
                              void* d_out, int out_size)
{
    const int*   loc    = (const int*)  d_in[0];
    const int*   st     = (const int*)  d_in[1];
    const int*   ed     = (const int*)  d_in[2];
    const float* A      = (const float*)d_in[3];
    const float* W_loc  = (const float*)d_in[4];
    const float* b_loc  = (const float*)d_in[5];
    const float* emb_st = (const float*)d_in[6];
    const float* emb_ed = (const float*)d_in[7];
    float*       out    = (float*)d_out;

    // Kernel 1: Y = A @ W_loc (sparse-aware stream of A). 8 warps/block.
    const int warps_needed  = LOCN;                       // one warp per row
    const int blocks_spmm   = (warps_needed + 7) / 8;     // 1250
    spmm_rows_kernel<<<blocks_spmm, 256>>>(A, W_loc);

    // Kernel 2: gather + concat + scale.
    constexpr int total = BB * SS * DSUM + BB * SS * DST;
    gather_concat_kernel<<<(total + 255) / 256, 256>>>(
        loc, st, ed, b_loc, emb_st, emb_ed, out);
}

// round 2
// speedup vs baseline: 1.7601x; 1.7601x over previous
#include <cuda_runtime.h>
#include <cstdint>

// Problem constants (fixed shapes from the reference)
#define LOCN  10000   // location vocab / A dimension
#define DLOC  128     // d_model for location branch
#define DST   64      // d_model for start-time / end branch
#define DSUM  256     // DLOC + DST + DST
#define BB    64      // batch
#define SS    128     // sequence length

// Scratch: Y = relu(A @ W_loc + b) * 16 for NEEDED rows only. 5.12 MB.
__device__ float g_Y[(size_t)LOCN * DLOC];
// Per-row "needed" flags (rows referenced by loc).
__device__ int   g_flag[LOCN];

// ---------------------------------------------------------------------------
// Kernel 0: clear flags.
// ---------------------------------------------------------------------------
__global__ void clear_flags_kernel()
{
    const int i = blockIdx.x * blockDim.x + threadIdx.x;
    if (i < LOCN) g_flag[i] = 0;
}

// ---------------------------------------------------------------------------
// Kernel 1: mark rows referenced by loc.
// ---------------------------------------------------------------------------
__global__ void mark_rows_kernel(const int* __restrict__ loc)
{
    const int i = blockIdx.x * blockDim.x + threadIdx.x;
    if (i < BB * SS) g_flag[loc[i]] = 1;
}

// ---------------------------------------------------------------------------
// Kernel 2: sparse-aware Y = relu(A @ W_loc + b) * 16, flagged rows only.
// One warp per row. Each lane streams TWO float4 per iteration (coalesced,
// 1 KB/warp/iter) to raise MLP; ballot over nonzero vectors (~0.1% density),
// broadcast hits via shfl, accumulate val * W_loc[n][:] into 4 regs/lane.
// ---------------------------------------------------------------------------
__global__ void __launch_bounds__(256) spmm_rows_kernel(
    const float* __restrict__ A, const float* __restrict__ W,
    const float* __restrict__ bias)
{
    const int warp_id = (blockIdx.x * blockDim.x + threadIdx.x) >> 5;
    const int lane    = threadIdx.x & 31;
    if (warp_id >= LOCN) return;
    if (!g_flag[warp_id]) return;            // row never gathered — skip

    const float4* __restrict__ row =
        reinterpret_cast<const float4*>(A + (size_t)warp_id * LOCN);

    float acc0 = 0.f, acc1 = 0.f, acc2 = 0.f, acc3 = 0.f;

    constexpr int NV4   = LOCN / 4;              // 2500 float4 per row
    constexpr int NITER = (NV4 + 63) / 64;       // 40 (last iter partial)

    for (int it = 0; it < NITER; ++it) {
        const int b0 = it * 64 + lane;
        const int b1 = b0 + 32;
        float4 v0, v1;
        if (b0 < NV4) v0 = __ldcs(&row[b0]);
        else          v0 = make_float4(0.f, 0.f, 0.f, 0.f);
        if (b1 < NV4) v1 = __ldcs(&row[b1]);
        else          v1 = make_float4(0.f, 0.f, 0.f, 0.f);

        const bool nz0 = (v0.x != 0.f) | (v0.y != 0.f) | (v0.z != 0.f) | (v0.w != 0.f);
        const bool nz1 = (v1.x != 0.f) | (v1.y != 0.f) | (v1.z != 0.f) | (v1.w != 0.f);
        unsigned m0 = __ballot_sync(0xffffffffu, nz0);
        unsigned m1 = __ballot_sync(0xffffffffu, nz1);

        #pragma unroll
        for (int half = 0; half < 2; ++half) {
            unsigned m = half ? m1 : m0;
            while (m) {
                const int j = __ffs(m) - 1;
                m &= m - 1;
                float vx, vy, vz, vw;
                if (half) {
                    vx = __shfl_sync(0xffffffffu, v1.x, j);
                    vy = __shfl_sync(0xffffffffu, v1.y, j);
                    vz = __shfl_sync(0xffffffffu, v1.z, j);
                    vw = __shfl_sync(0xffffffffu, v1.w, j);
                } else {
                    vx = __shfl_sync(0xffffffffu, v0.x, j);
                    vy = __shfl_sync(0xffffffffu, v0.y, j);
                    vz = __shfl_sync(0xffffffffu, v0.z, j);
                    vw = __shfl_sync(0xffffffffu, v0.w, j);
                }
                const int n0 = (it * 64 + half * 32 + j) * 4;

                const float* __restrict__ Wr = W + (size_t)n0 * DLOC + lane;
                if (vx != 0.f) {
                    acc0 = fmaf(vx, Wr[0],  acc0);
                    acc1 = fmaf(vx, Wr[32], acc1);
                    acc2 = fmaf(vx, Wr[64], acc2);
                    acc3 = fmaf(vx, Wr[96], acc3);
                }
                Wr += DLOC;
                if (vy != 0.f) {
                    acc0 = fmaf(vy, Wr[0],  acc0);
                    acc1 = fmaf(vy, Wr[32], acc1);
                    acc2 = fmaf(vy, Wr[64], acc2);
                    acc3 = fmaf(vy, Wr[96], acc3);
                }
                Wr += DLOC;
                if (vz != 0.f) {
                    acc0 = fmaf(vz, Wr[0],  acc0);
                    acc1 = fmaf(vz, Wr[32], acc1);
                    acc2 = fmaf(vz, Wr[64], acc2);
                    acc3 = fmaf(vz, Wr[96], acc3);
                }
                Wr += DLOC;
                if (vw != 0.f) {
                    acc0 = fmaf(vw, Wr[0],  acc0);
                    acc1 = fmaf(vw, Wr[32], acc1);
                    acc2 = fmaf(vw, Wr[64], acc2);
                    acc3 = fmaf(vw, Wr[96], acc3);
                }
            }
        }
    }

    // Fused epilogue: relu(acc + bias) * sqrt(DSUM)
    const float s = 16.0f;
    float b0v = bias[lane], b1v = bias[lane + 32],
          b2v = bias[lane + 64], b3v = bias[lane + 96];
    float* __restrict__ y = g_Y + (size_t)warp_id * DLOC + lane;
    y[0]  = fmaxf(acc0 + b0v, 0.f) * s;
    y[32] = fmaxf(acc1 + b1v, 0.f) * s;
    y[64] = fmaxf(acc2 + b2v, 0.f) * s;
    y[96] = fmaxf(acc3 + b3v, 0.f) * s;
}

// ---------------------------------------------------------------------------
// Kernel 3: assemble outputs, vectorized float4.
//   out[0 : B*S*256)        = concat(Y[loc], emb_st[st]*16, emb_ed[ed]*16)
//   out[B*S*256 : +B*S*64)  = emb_st[yt], yt[b,s] = st[b,s+1] (0 at s=S-1)
// ---------------------------------------------------------------------------
__global__ void __launch_bounds__(256) gather_concat_kernel(
    const int*   __restrict__ loc,
    const int*   __restrict__ st,
    const int*   __restrict__ ed,
    const float* __restrict__ emb_st,
    const float* __restrict__ emb_ed,
    float4*      __restrict__ out)
{
    const int idx = blockIdx.x * blockDim.x + threadIdx.x;
    constexpr int N1V = BB * SS * DSUM / 4;          // 524288 float4
    constexpr int NTV = N1V + BB * SS * DST / 4;     // 655360 float4
    if (idx >= NTV) return;

    const float4* __restrict__ Yv  = reinterpret_cast<const float4*>(g_Y);
    const float4* __restrict__ stv = reinterpret_cast<const float4*>(emb_st);
    const float4* __restrict__ edv = reinterpret_cast<const float4*>(emb_ed);
    const float s = 16.0f;

    if (idx < N1V) {
        const int bs = idx >> 6;                     // / (DSUM/4)
        const int d4 = idx & 63;
        float4 r;
        if (d4 < 32) {                               // loc branch (pre-scaled)
            r = Yv[(size_t)loc[bs] * 32 + d4];
        } else if (d4 < 48) {                        // st branch
            r = stv[st[bs] * 16 + (d4 - 32)];
            r.x *= s; r.y *= s; r.z *= s; r.w *= s;
        } else {                                     // ed branch
            r = edv[ed[bs] * 16 + (d4 - 48)];
            r.x *= s; r.y *= s; r.z *= s; r.w *= s;
        }
        out[idx] = r;
    } else {
        const int j  = idx - N1V;
        const int bs = j >> 4;                       // / (DST/4)
        const int d4 = j & 15;
        const int ss = bs & (SS - 1);
        const int yt = (ss < SS - 1) ? st[bs + 1] : 0;
        out[idx] = stv[yt * 16 + d4];                // res_yt is NOT scaled
    }
}

extern "C" void kernel_launch(void* const* d_in, const int* in_sizes, int n_in,
                              void* d_out, int out_size)
{
    const int*   loc    = (const int*)  d_in[0];
    const int*   st     = (const int*)  d_in[1];
    const int*   ed     = (const int*)  d_in[2];
    const float* A      = (const float*)d_in[3];
    const float* W_loc  = (const float*)d_in[4];
    const float* b_loc  = (const float*)d_in[5];
    const float* emb_st = (const float*)d_in[6];
    const float* emb_ed = (const float*)d_in[7];

    clear_flags_kernel<<<(LOCN + 255) / 256, 256>>>();
    mark_rows_kernel<<<(BB * SS + 255) / 256, 256>>>(loc);

    // SpMM over flagged rows only: one warp per row, 8 warps/block.
    spmm_rows_kernel<<<(LOCN + 7) / 8, 256>>>(A, W_loc, b_loc);

    constexpr int totalv = (BB * SS * DSUM + BB * SS * DST) / 4;
    gather_concat_kernel<<<(totalv + 255) / 256, 256>>>(
        loc, st, ed, emb_st, emb_ed, (float4*)d_out);
}

// round 3
// speedup vs baseline: 2.1952x; 1.2472x over previous
#include <cuda_runtime.h>
#include <cstdint>

#define LOCN  10000
#define DLOC  128
#define DST   64
#define DSUM  256
#define BB    64
#define SS    128
#define NROWS_MAX (BB * SS)   // max unique rows = 8192

// Scratch: Y = relu(A @ W_loc + b)*16 for needed rows (5.12 MB).
__device__ float g_Y[(size_t)LOCN * DLOC];
__device__ int   g_flag[LOCN];
__device__ int   g_list[NROWS_MAX];
__device__ int   g_count;

// ---------------------------------------------------------------------------
// Kernel 0: clear flags + counter.
// ---------------------------------------------------------------------------
__global__ void clear_flags_kernel()
{
    const int i = blockIdx.x * blockDim.x + threadIdx.x;
    if (i < LOCN) g_flag[i] = 0;
    if (i == 0)   g_count   = 0;
}

// ---------------------------------------------------------------------------
// Kernel 1: compact unique loc rows into g_list.
// ---------------------------------------------------------------------------
__global__ void mark_compact_kernel(const int* __restrict__ loc)
{
    const int i = blockIdx.x * blockDim.x + threadIdx.x;
    if (i < BB * SS) {
        const int r = loc[i];
        if (atomicExch(&g_flag[r], 1) == 0) {
            const int p = atomicAdd(&g_count, 1);
            g_list[p] = r;
        }
    }
}

// ---------------------------------------------------------------------------
// Kernel 2: Y = relu(A@W + b)*16 for listed rows. One warp per row.
// 4 float4/lane/iter (2 KB/warp/iter) + next-iter prefetch before the
// ballot-processing of the current iter => ~8 loads in flight per lane.
// ---------------------------------------------------------------------------
__global__ void __launch_bounds__(256) spmm_rows_kernel(
    const float* __restrict__ A, const float* __restrict__ W,
    const float* __restrict__ bias)
{
    const int warp_id = (blockIdx.x * blockDim.x + threadIdx.x) >> 5;
    const int lane    = threadIdx.x & 31;
    if (warp_id >= g_count) return;
    const int row_idx = g_list[warp_id];

    const float4* __restrict__ row =
        reinterpret_cast<const float4*>(A + (size_t)row_idx * LOCN);

    constexpr int NV4   = LOCN / 4;                    // 2500
    constexpr int VPI   = 128;                         // float4 per warp per iter
    constexpr int NITER = (NV4 + VPI - 1) / VPI;       // 20

    float acc0 = 0.f, acc1 = 0.f, acc2 = 0.f, acc3 = 0.f;
    const float4 Z = make_float4(0.f, 0.f, 0.f, 0.f);

    float4 cur[4], nxt[4];
    {
        const int base = lane;
        #pragma unroll
        for (int k = 0; k < 4; ++k) {
            const int idx = base + 32 * k;
            cur[k] = (idx < NV4) ? __ldcs(&row[idx]) : Z;
        }
    }

    for (int it = 0; it < NITER; ++it) {
        const int nbase = (it + 1) * VPI + lane;
        if (it + 1 < NITER) {
            #pragma unroll
            for (int k = 0; k < 4; ++k) {
                const int idx = nbase + 32 * k;
                nxt[k] = (idx < NV4) ? __ldcs(&row[idx]) : Z;
            }
        }

        #pragma unroll
        for (int k = 0; k < 4; ++k) {
            const float4 v = cur[k];
            const bool nz = (v.x != 0.f) | (v.y != 0.f) | (v.z != 0.f) | (v.w != 0.f);
            unsigned m = __ballot_sync(0xffffffffu, nz);
            while (m) {
                const int j = __ffs(m) - 1;
                m &= m - 1;
                const float vx = __shfl_sync(0xffffffffu, v.x, j);
                const float vy = __shfl_sync(0xffffffffu, v.y, j);
                const float vz = __shfl_sync(0xffffffffu, v.z, j);
                const float vw = __shfl_sync(0xffffffffu, v.w, j);
                const int n0 = (it * VPI + k * 32 + j) * 4;

                const float* __restrict__ Wr = W + (size_t)n0 * DLOC + lane;
                if (vx != 0.f) {
                    acc0 = fmaf(vx, Wr[0],  acc0);
                    acc1 = fmaf(vx, Wr[32], acc1);
                    acc2 = fmaf(vx, Wr[64], acc2);
                    acc3 = fmaf(vx, Wr[96], acc3);
                }
                Wr += DLOC;
                if (vy != 0.f) {
                    acc0 = fmaf(vy, Wr[0],  acc0);
                    acc1 = fmaf(vy, Wr[32], acc1);
                    acc2 = fmaf(vy, Wr[64], acc2);
                    acc3 = fmaf(vy, Wr[96], acc3);
                }
                Wr += DLOC;
                if (vz != 0.f) {
                    acc0 = fmaf(vz, Wr[0],  acc0);
                    acc1 = fmaf(vz, Wr[32], acc1);
                    acc2 = fmaf(vz, Wr[64], acc2);
                    acc3 = fmaf(vz, Wr[96], acc3);
                }
                Wr += DLOC;
                if (vw != 0.f) {
                    acc0 = fmaf(vw, Wr[0],  acc0);
                    acc1 = fmaf(vw, Wr[32], acc1);
                    acc2 = fmaf(vw, Wr[64], acc2);
                    acc3 = fmaf(vw, Wr[96], acc3);
                }
            }
        }

        #pragma unroll
        for (int k = 0; k < 4; ++k) cur[k] = nxt[k];
    }

    // Fused epilogue: relu(acc + bias) * sqrt(DSUM)
    const float s = 16.0f;
    float* __restrict__ y = g_Y + (size_t)row_idx * DLOC + lane;
    y[0]  = fmaxf(acc0 + bias[lane],      0.f) * s;
    y[32] = fmaxf(acc1 + bias[lane + 32], 0.f) * s;
    y[64] = fmaxf(acc2 + bias[lane + 64], 0.f) * s;
    y[96] = fmaxf(acc3 + bias[lane + 96], 0.f) * s;
}

// ---------------------------------------------------------------------------
// Kernel 3: assemble outputs (float4). Each thread does 2 independent
// elements (idx, idx + HALF) for 2-deep MLP.
// ---------------------------------------------------------------------------
__global__ void __launch_bounds__(256) gather_concat_kernel(
    const int*   __restrict__ loc,
    const int*   __restrict__ st,
    const int*   __restrict__ ed,
    const float* __restrict__ emb_st,
    const float* __restrict__ emb_ed,
    float4*      __restrict__ out)
{
    constexpr int N1V  = BB * SS * DSUM / 4;           // 524288
    constexpr int NTV  = N1V + BB * SS * DST / 4;      // 655360
    constexpr int HALF = NTV / 2;                      // 327680

    const int tid = blockIdx.x * blockDim.x + threadIdx.x;
    if (tid >= HALF) return;

    const float4* __restrict__ Yv  = reinterpret_cast<const float4*>(g_Y);
    const float4* __restrict__ stv = reinterpret_cast<const float4*>(emb_st);
    const float4* __restrict__ edv = reinterpret_cast<const float4*>(emb_ed);
    const float s = 16.0f;

    #pragma unroll
    for (int h = 0; h < 2; ++h) {
        const int idx = tid + h * HALF;
        float4 r;
        if (idx < N1V) {
            const int bs = idx >> 6;
            const int d4 = idx & 63;
            if (d4 < 32) {                               // loc (pre-scaled)
                r = Yv[(size_t)loc[bs] * 32 + d4];
            } else if (d4 < 48) {                        // st
                r = stv[st[bs] * 16 + (d4 - 32)];
                r.x *= s; r.y *= s; r.z *= s; r.w *= s;
            } else {                                     // ed
                r = edv[ed[bs] * 16 + (d4 - 48)];
                r.x *= s; r.y *= s; r.z *= s; r.w *= s;
            }
        } else {
            const int j  = idx - N1V;
            const int bs = j >> 4;
            const int d4 = j & 15;
            const int ss = bs & (SS - 1);
            const int yt = (ss < SS - 1) ? st[bs + 1] : 0;
            r = stv[yt * 16 + d4];                       // res_yt NOT scaled
        }
        out[idx] = r;
    }
}

extern "C" void kernel_launch(void* const* d_in, const int* in_sizes, int n_in,
                              void* d_out, int out_size)
{
    const int*   loc    = (const int*)  d_in[0];
    const int*   st     = (const int*)  d_in[1];
    const int*   ed     = (const int*)  d_in[2];
    const float* A      = (const float*)d_in[3];
    const float* W_loc  = (const float*)d_in[4];
    const float* b_loc  = (const float*)d_in[5];
    const float* emb_st = (const float*)d_in[6];
    const float* emb_ed = (const float*)d_in[7];

    clear_flags_kernel<<<(LOCN + 255) / 256, 256>>>();
    mark_compact_kernel<<<(BB * SS + 255) / 256, 256>>>(loc);

    // Worst case 8192 unique rows; inactive warps exit on g_count check.
    spmm_rows_kernel<<<NROWS_MAX / 8, 256>>>(A, W_loc, b_loc);

    constexpr int half = (BB * SS * DSUM + BB * SS * DST) / 4 / 2;
    gather_concat_kernel<<<(half + 255) / 256, 256>>>(
        loc, st, ed, emb_st, emb_ed, (float4*)d_out);
}

// round 4
// speedup vs baseline: 2.3653x; 1.0775x over previous
#include <cuda_runtime.h>
#include <cstdint>

#define LOCN  10000
#define DLOC  128
#define DST   64
#define DSUM  256
#define BB    64
#define SS    128
#define NROWS_MAX (BB * SS)   // max unique rows = 8192

// Scratch: Y = relu(A @ W_loc + b)*16 for needed rows (5.12 MB).
__device__ float g_Y[(size_t)LOCN * DLOC];
__device__ int   g_flag[LOCN];   // zero-init; re-cleared by gather kernel
__device__ int   g_list[NROWS_MAX];
__device__ int   g_count;        // zero-init; reset by gather kernel

// ---------------------------------------------------------------------------
// Kernel 1: compact unique loc rows into g_list. (flags are clean on entry)
// ---------------------------------------------------------------------------
__global__ void mark_compact_kernel(const int* __restrict__ loc)
{
    const int i = blockIdx.x * blockDim.x + threadIdx.x;
    if (i < BB * SS) {
        const int r = loc[i];
        if (atomicExch(&g_flag[r], 1) == 0) {
            const int p = atomicAdd(&g_count, 1);
            g_list[p] = r;
        }
    }
}

// ---------------------------------------------------------------------------
// Kernel 2: Y = relu(A@W + b)*16 for listed rows. One warp per row.
// 8 float4/lane/iter (4 KB/warp/iter, 10 iters) with full next-iter prefetch
// issued before processing => up to 16 loads in flight per lane.
// ---------------------------------------------------------------------------
__global__ void __launch_bounds__(256, 2) spmm_rows_kernel(
    const float* __restrict__ A, const float* __restrict__ W,
    const float* __restrict__ bias)
{
    const int warp_id = (blockIdx.x * blockDim.x + threadIdx.x) >> 5;
    const int lane    = threadIdx.x & 31;
    if (warp_id >= g_count) return;
    const int row_idx = g_list[warp_id];

    const float4* __restrict__ row =
        reinterpret_cast<const float4*>(A + (size_t)row_idx * LOCN);

    constexpr int NV4   = LOCN / 4;                    // 2500
    constexpr int K     = 8;                           // float4 per lane per iter
    constexpr int VPI   = 32 * K;                      // 256 float4/warp/iter
    constexpr int NITER = (NV4 + VPI - 1) / VPI;       // 10

    float acc0 = 0.f, acc1 = 0.f, acc2 = 0.f, acc3 = 0.f;
    const float4 Z = make_float4(0.f, 0.f, 0.f, 0.f);

    float4 cur[K], nxt[K];
    #pragma unroll
    for (int k = 0; k < K; ++k) {
        const int idx = lane + 32 * k;
        cur[k] = (idx < NV4) ? __ldcs(&row[idx]) : Z;
    }

    for (int it = 0; it < NITER; ++it) {
        if (it + 1 < NITER) {
            const int nbase = (it + 1) * VPI + lane;
            #pragma unroll
            for (int k = 0; k < K; ++k) {
                const int idx = nbase + 32 * k;
                nxt[k] = (idx < NV4) ? __ldcs(&row[idx]) : Z;
            }
        }

        #pragma unroll
        for (int k = 0; k < K; ++k) {
            const float4 v = cur[k];
            const bool nz = (v.x != 0.f) | (v.y != 0.f) | (v.z != 0.f) | (v.w != 0.f);
            unsigned m = __ballot_sync(0xffffffffu, nz);
            while (m) {
                const int j = __ffs(m) - 1;
                m &= m - 1;
                const float vx = __shfl_sync(0xffffffffu, v.x, j);
                const float vy = __shfl_sync(0xffffffffu, v.y, j);
                const float vz = __shfl_sync(0xffffffffu, v.z, j);
                const float vw = __shfl_sync(0xffffffffu, v.w, j);
                const int n0 = (it * VPI + k * 32 + j) * 4;

                const float* __restrict__ Wr = W + (size_t)n0 * DLOC + lane;
                if (vx != 0.f) {
                    acc0 = fmaf(vx, Wr[0],  acc0);
                    acc1 = fmaf(vx, Wr[32], acc1);
                    acc2 = fmaf(vx, Wr[64], acc2);
                    acc3 = fmaf(vx, Wr[96], acc3);
                }
                Wr += DLOC;
                if (vy != 0.f) {
                    acc0 = fmaf(vy, Wr[0],  acc0);
                    acc1 = fmaf(vy, Wr[32], acc1);
                    acc2 = fmaf(vy, Wr[64], acc2);
                    acc3 = fmaf(vy, Wr[96], acc3);
                }
                Wr += DLOC;
                if (vz != 0.f) {
                    acc0 = fmaf(vz, Wr[0],  acc0);
                    acc1 = fmaf(vz, Wr[32], acc1);
                    acc2 = fmaf(vz, Wr[64], acc2);
                    acc3 = fmaf(vz, Wr[96], acc3);
                }
                Wr += DLOC;
                if (vw != 0.f) {
                    acc0 = fmaf(vw, Wr[0],  acc0);
                    acc1 = fmaf(vw, Wr[32], acc1);
                    acc2 = fmaf(vw, Wr[64], acc2);
                    acc3 = fmaf(vw, Wr[96], acc3);
                }
            }
        }

        #pragma unroll
        for (int k = 0; k < K; ++k) cur[k] = nxt[k];
    }

    // Fused epilogue: relu(acc + bias) * sqrt(DSUM)
    const float s = 16.0f;
    float* __restrict__ y = g_Y + (size_t)row_idx * DLOC + lane;
    y[0]  = fmaxf(acc0 + bias[lane],      0.f) * s;
    y[32] = fmaxf(acc1 + bias[lane + 32], 0.f) * s;
    y[64] = fmaxf(acc2 + bias[lane + 64], 0.f) * s;
    y[96] = fmaxf(acc3 + bias[lane + 96], 0.f) * s;
}

// ---------------------------------------------------------------------------
// Kernel 3: assemble outputs (float4), 2 independent elements per thread.
// Also re-clears g_flag / g_count for the next replay (graph-safe: this is
// the last kernel, and mark_compact of the next call runs after it).
// ---------------------------------------------------------------------------
__global__ void __launch_bounds__(256) gather_concat_kernel(
    const int*   __restrict__ loc,
    const int*   __restrict__ st,
    const int*   __restrict__ ed,
    const float* __restrict__ emb_st,
    const float* __restrict__ emb_ed,
    float4*      __restrict__ out)
{
    constexpr int N1V  = BB * SS * DSUM / 4;           // 524288
    constexpr int NTV  = N1V + BB * SS * DST / 4;      // 655360
    constexpr int HALF = NTV / 2;                      // 327680

    const int tid = blockIdx.x * blockDim.x + threadIdx.x;
    if (tid >= HALF) return;

    // Cleanup for next launch: clear flags of listed rows, reset counter.
    // Stale g_list entries may clear already-zero flags — harmless.
    if (tid < NROWS_MAX) g_flag[g_list[tid]] = 0;
    if (tid == 0)        g_count = 0;

    const float4* __restrict__ Yv  = reinterpret_cast<const float4*>(g_Y);
    const float4* __restrict__ stv = reinterpret_cast<const float4*>(emb_st);
    const float4* __restrict__ edv = reinterpret_cast<const float4*>(emb_ed);
    const float s = 16.0f;

    #pragma unroll
    for (int h = 0; h < 2; ++h) {
        const int idx = tid + h * HALF;
        float4 r;
        if (idx < N1V) {
            const int bs = idx >> 6;
            const int d4 = idx & 63;
            if (d4 < 32) {                               // loc (pre-scaled)
                r = Yv[(size_t)loc[bs] * 32 + d4];
            } else if (d4 < 48) {                        // st
                r = stv[st[bs] * 16 + (d4 - 32)];
                r.x *= s; r.y *= s; r.z *= s; r.w *= s;
            } else {                                     // ed
                r = edv[ed[bs] * 16 + (d4 - 48)];
                r.x *= s; r.y *= s; r.z *= s; r.w *= s;
            }
        } else {
            const int j  = idx - N1V;
            const int bs = j >> 4;
            const int d4 = j & 15;
            const int ss = bs & (SS - 1);
            const int yt = (ss < SS - 1) ? st[bs + 1] : 0;
            r = stv[yt * 16 + d4];                       // res_yt NOT scaled
        }
        out[idx] = r;
    }
}

extern "C" void kernel_launch(void* const* d_in, const int* in_sizes, int n_in,
                              void* d_out, int out_size)
{
    const int*   loc    = (const int*)  d_in[0];
    const int*   st     = (const int*)  d_in[1];
    const int*   ed     = (const int*)  d_in[2];
    const float* A      = (const float*)d_in[3];
    const float* W_loc  = (const float*)d_in[4];
    const float* b_loc  = (const float*)d_in[5];
    const float* emb_st = (const float*)d_in[6];
    const float* emb_ed = (const float*)d_in[7];

    mark_compact_kernel<<<(BB * SS + 255) / 256, 256>>>(loc);

    // Worst case 8192 unique rows; inactive warps exit on g_count check.
    spmm_rows_kernel<<<NROWS_MAX / 8, 256>>>(A, W_loc, b_loc);

    constexpr int half = (BB * SS * DSUM + BB * SS * DST) / 4 / 2;
    gather_concat_kernel<<<(half + 255) / 256, 256>>>(
        loc, st, ed, emb_st, emb_ed, (float4*)d_out);
}

// round 5
// speedup vs baseline: 2.4470x; 1.0345x over previous
#include <cuda_runtime.h>
#include <cstdint>

#define LOCN  10000
#define DLOC  128
#define DST   64
#define DSUM  256
#define BB    64
#define SS    128
#define NROWS_MAX (BB * SS)   // max unique rows = 8192

// Scratch: Y = relu(A @ W_loc + b)*16 for needed rows (5.12 MB).
__device__ float g_Y[(size_t)LOCN * DLOC];
__device__ int   g_list[NROWS_MAX];
__device__ int   g_count;   // number of unique rows (set by mark_compact)
__device__ int   g_work;    // work-stealing cursor (reset by mark_compact)

// ---------------------------------------------------------------------------
// Kernel 1: single-block dedup/compact of loc into g_list using smem flags.
// 1024 threads x 8 elems; smem atomics (32 cyc) instead of L2 atomics (~318).
// Fully self-contained per launch: no persistent state to clean up.
// ---------------------------------------------------------------------------
__global__ void __launch_bounds__(1024) mark_compact_kernel(
    const int* __restrict__ loc)
{
    __shared__ int s_flag[LOCN];
    __shared__ int s_count;

    const int t = threadIdx.x;
    for (int i = t; i < LOCN; i += 1024) s_flag[i] = 0;
    if (t == 0) s_count = 0;
    __syncthreads();

    #pragma unroll
    for (int k = 0; k < (BB * SS) / 1024; ++k) {
        const int r = loc[t + k * 1024];
        if (atomicExch(&s_flag[r], 1) == 0) {
            const int p = atomicAdd(&s_count, 1);
            g_list[p] = r;
        }
    }
    __syncthreads();

    if (t == 0) {
        g_count = s_count;
        g_work  = 0;
    }
}

// ---------------------------------------------------------------------------
// Kernel 2: Y = relu(A@W + b)*16. Persistent warps; each warp pops row
// indices from g_work (no wave quantization). Per row: 8 float4/lane/iter
// with next-iter prefetch => up to 16 loads in flight per lane.
// ---------------------------------------------------------------------------
__global__ void __launch_bounds__(256, 2) spmm_rows_kernel(
    const float* __restrict__ A, const float* __restrict__ W,
    const float* __restrict__ bias)
{
    const int lane  = threadIdx.x & 31;
    const int count = g_count;

    constexpr int NV4   = LOCN / 4;                    // 2500
    constexpr int K     = 8;                           // float4 per lane per iter
    constexpr int VPI   = 32 * K;                      // 256 float4/warp/iter
    constexpr int NITER = (NV4 + VPI - 1) / VPI;       // 10
    const float4 Z = make_float4(0.f, 0.f, 0.f, 0.f);

    const float b0v = bias[lane];
    const float b1v = bias[lane + 32];
    const float b2v = bias[lane + 64];
    const float b3v = bias[lane + 96];

    for (;;) {
        int widx = 0;
        if (lane == 0) widx = atomicAdd(&g_work, 1);
        widx = __shfl_sync(0xffffffffu, widx, 0);
        if (widx >= count) return;
        const int row_idx = g_list[widx];

        const float4* __restrict__ row =
            reinterpret_cast<const float4*>(A + (size_t)row_idx * LOCN);

        float acc0 = 0.f, acc1 = 0.f, acc2 = 0.f, acc3 = 0.f;

        float4 cur[K], nxt[K];
        #pragma unroll
        for (int k = 0; k < K; ++k) {
            const int idx = lane + 32 * k;
            cur[k] = (idx < NV4) ? __ldcs(&row[idx]) : Z;
        }

        for (int it = 0; it < NITER; ++it) {
            if (it + 1 < NITER) {
                const int nbase = (it + 1) * VPI + lane;
                #pragma unroll
                for (int k = 0; k < K; ++k) {
                    const int idx = nbase + 32 * k;
                    nxt[k] = (idx < NV4) ? __ldcs(&row[idx]) : Z;
                }
            }

            #pragma unroll
            for (int k = 0; k < K; ++k) {
                const float4 v = cur[k];
                const bool nz = (v.x != 0.f) | (v.y != 0.f) |
                                (v.z != 0.f) | (v.w != 0.f);
                unsigned m = __ballot_sync(0xffffffffu, nz);
                while (m) {
                    const int j = __ffs(m) - 1;
                    m &= m - 1;
                    const float vx = __shfl_sync(0xffffffffu, v.x, j);
                    const float vy = __shfl_sync(0xffffffffu, v.y, j);
                    const float vz = __shfl_sync(0xffffffffu, v.z, j);
                    const float vw = __shfl_sync(0xffffffffu, v.w, j);
                    const int n0 = (it * VPI + k * 32 + j) * 4;

                    const float* __restrict__ Wr = W + (size_t)n0 * DLOC + lane;
                    if (vx != 0.f) {
                        acc0 = fmaf(vx, Wr[0],  acc0);
                        acc1 = fmaf(vx, Wr[32], acc1);
                        acc2 = fmaf(vx, Wr[64], acc2);
                        acc3 = fmaf(vx, Wr[96], acc3);
                    }
                    Wr += DLOC;
                    if (vy != 0.f) {
                        acc0 = fmaf(vy, Wr[0],  acc0);
                        acc1 = fmaf(vy, Wr[32], acc1);
                        acc2 = fmaf(vy, Wr[64], acc2);
                        acc3 = fmaf(vy, Wr[96], acc3);
                    }
                    Wr += DLOC;
                    if (vz != 0.f) {
                        acc0 = fmaf(vz, Wr[0],  acc0);
                        acc1 = fmaf(vz, Wr[32], acc1);
                        acc2 = fmaf(vz, Wr[64], acc2);
                        acc3 = fmaf(vz, Wr[96], acc3);
                    }
                    Wr += DLOC;
                    if (vw != 0.f) {
                        acc0 = fmaf(vw, Wr[0],  acc0);
                        acc1 = fmaf(vw, Wr[32], acc1);
                        acc2 = fmaf(vw, Wr[64], acc2);
                        acc3 = fmaf(vw, Wr[96], acc3);
                    }
                }
            }

            #pragma unroll
            for (int k = 0; k < K; ++k) cur[k] = nxt[k];
        }

        const float s = 16.0f;
        float* __restrict__ y = g_Y + (size_t)row_idx * DLOC + lane;
        y[0]  = fmaxf(acc0 + b0v, 0.f) * s;
        y[32] = fmaxf(acc1 + b1v, 0.f) * s;
        y[64] = fmaxf(acc2 + b2v, 0.f) * s;
        y[96] = fmaxf(acc3 + b3v, 0.f) * s;
    }
}

// ---------------------------------------------------------------------------
// Kernel 3: assemble outputs (float4), 4 independent elements per thread.
// ---------------------------------------------------------------------------
__global__ void __launch_bounds__(256) gather_concat_kernel(
    const int*   __restrict__ loc,
    const int*   __restrict__ st,
    const int*   __restrict__ ed,
    const float* __restrict__ emb_st,
    const float* __restrict__ emb_ed,
    float4*      __restrict__ out)
{
    constexpr int N1V  = BB * SS * DSUM / 4;           // 524288
    constexpr int NTV  = N1V + BB * SS * DST / 4;      // 655360
    constexpr int QTR  = NTV / 4;                      // 163840

    const int tid = blockIdx.x * blockDim.x + threadIdx.x;
    if (tid >= QTR) return;

    const float4* __restrict__ Yv  = reinterpret_cast<const float4*>(g_Y);
    const float4* __restrict__ stv = reinterpret_cast<const float4*>(emb_st);
    const float4* __restrict__ edv = reinterpret_cast<const float4*>(emb_ed);
    const float s = 16.0f;

    #pragma unroll
    for (int h = 0; h < 4; ++h) {
        const int idx = tid + h * QTR;
        float4 r;
        if (idx < N1V) {
            const int bs = idx >> 6;
            const int d4 = idx & 63;
            if (d4 < 32) {                               // loc (pre-scaled)
                r = Yv[(size_t)loc[bs] * 32 + d4];
            } else if (d4 < 48) {                        // st
                r = stv[st[bs] * 16 + (d4 - 32)];
                r.x *= s; r.y *= s; r.z *= s; r.w *= s;
            } else {                                     // ed
                r = edv[ed[bs] * 16 + (d4 - 48)];
                r.x *= s; r.y *= s; r.z *= s; r.w *= s;
            }
        } else {
            const int j  = idx - N1V;
            const int bs = j >> 4;
            const int d4 = j & 15;
            const int ss = bs & (SS - 1);
            const int yt = (ss < SS - 1) ? st[bs + 1] : 0;
            r = stv[yt * 16 + d4];                       // res_yt NOT scaled
        }
        out[idx] = r;
    }
}

extern "C" void kernel_launch(void* const* d_in, const int* in_sizes, int n_in,
                              void* d_out, int out_size)
{
    const int*   loc    = (const int*)  d_in[0];
    const int*   st     = (const int*)  d_in[1];
    const int*   ed     = (const int*)  d_in[2];
    const float* A      = (const float*)d_in[3];
    const float* W_loc  = (const float*)d_in[4];
    const float* b_loc  = (const float*)d_in[5];
    const float* emb_st = (const float*)d_in[6];
    const float* emb_ed = (const float*)d_in[7];

    mark_compact_kernel<<<1, 1024>>>(loc);

    // Persistent work-stealing: 2 blocks/SM x 148 SMs.
    spmm_rows_kernel<<<296, 256>>>(A, W_loc, b_loc);

    constexpr int qtr = (BB * SS * DSUM + BB * SS * DST) / 4 / 4;
    gather_concat_kernel<<<(qtr + 255) / 256, 256>>>(
        loc, st, ed, emb_st, emb_ed, (float4*)d_out);
}